// round 1
// baseline (speedup 1.0000x reference)
#include <cuda_runtime.h>
#include <math.h>

// ---------------------------------------------------------------------------
// NRAE loss, collapsed form (hess == 0 for ReLU MLP decoder):
//   z = enc(x);  recon = dec(z_c);  jac = (((dz@Wd1)*m1)@Wd2*m2)@Wd3
//   loss = mean_r  w[r] * sum_d (x_nn[r,d] - recon[b,d] - jac[r,d])^2
// ---------------------------------------------------------------------------

#define BM 128
#define BN 128
#define BK 8
#define TM 8
#define TN 8

#define D_DIM 3072
#define H_DIM 1024
#define Z_DIM 32
#define BS    128
#define NN    32
#define RTOT  (BS*NN)   // 4096

enum { EPI_BIAS_RELU = 0, EPI_BIAS = 1, EPI_MASK = 2, EPI_LOSS = 3 };

// scratch (static device globals; no allocation)
__device__ float g_H1   [RTOT * H_DIM];
__device__ float g_H2   [RTOT * H_DIM];
__device__ float g_H1c  [BS * H_DIM];
__device__ float g_H2c  [BS * H_DIM];
__device__ float g_Zn   [RTOT * Z_DIM];
__device__ float g_Zc   [BS * Z_DIM];
__device__ float g_h1d  [BS * H_DIM];
__device__ float g_h2d  [BS * H_DIM];
__device__ float g_recon[BS * D_DIM];
__device__ float g_dz   [RTOT * Z_DIM];
__device__ float g_t1   [RTOT * H_DIM];
__device__ float g_t2   [RTOT * H_DIM];
__device__ float g_w    [RTOT];
__device__ float g_loss;

// ---------------------------------------------------------------------------
// Tiled SGEMM: C(M,N) = epi(A(M,K) @ B(K,N)).  M%128==0, N%128==0, K%8==0.
// EPI_MASK : C = acc * (maskSrc[row>>5, col] > 0)
// EPI_LOSS : accumulate w[row]*(xnn[row,col]-recon[row>>5,col]-acc)^2 -> lossAcc
// ---------------------------------------------------------------------------
template <int EPI>
__global__ __launch_bounds__(256, 2)
void sgemm_k(const float* __restrict__ A, const float* __restrict__ B,
             float* __restrict__ C, int M, int N, int K,
             const float* __restrict__ bias,
             const float* __restrict__ maskSrc,
             const float* __restrict__ xnn,
             const float* __restrict__ recon,
             const float* __restrict__ wts,
             float* __restrict__ lossAcc)
{
    __shared__ float As[BK][BM];
    __shared__ float Bs[BK][BN];
    __shared__ float red[256];

    const int tid = threadIdx.x;
    const int bm = blockIdx.y * BM;
    const int bn = blockIdx.x * BN;

    const int arow = tid >> 1;          // 0..127
    const int acol = (tid & 1) * 4;     // 0 or 4
    const int brow = tid >> 5;          // 0..7
    const int bcol = (tid & 31) * 4;    // 0..124

    const float* Aptr = A + (size_t)(bm + arow) * K + acol;
    const float* Bptr = B + (size_t)brow * N + bn + bcol;

    float acc[TM][TN];
#pragma unroll
    for (int i = 0; i < TM; i++)
#pragma unroll
        for (int j = 0; j < TN; j++) acc[i][j] = 0.f;

    const int trow = (tid >> 4) * TM;   // 0..120
    const int tcol = (tid & 15) * TN;   // 0..120

    for (int k0 = 0; k0 < K; k0 += BK) {
        float4 av = *(const float4*)Aptr;
        float4 bv = *(const float4*)Bptr;
        As[acol + 0][arow] = av.x;
        As[acol + 1][arow] = av.y;
        As[acol + 2][arow] = av.z;
        As[acol + 3][arow] = av.w;
        *(float4*)&Bs[brow][bcol] = bv;
        __syncthreads();
#pragma unroll
        for (int kk = 0; kk < BK; kk++) {
            float ar[TM], br[TN];
#pragma unroll
            for (int i = 0; i < TM; i += 4)
                *(float4*)&ar[i] = *(const float4*)&As[kk][trow + i];
#pragma unroll
            for (int j = 0; j < TN; j += 4)
                *(float4*)&br[j] = *(const float4*)&Bs[kk][tcol + j];
#pragma unroll
            for (int i = 0; i < TM; i++)
#pragma unroll
                for (int j = 0; j < TN; j++)
                    acc[i][j] = fmaf(ar[i], br[j], acc[i][j]);
        }
        __syncthreads();
        Aptr += BK;
        Bptr += (size_t)BK * N;
    }

    if (EPI == EPI_LOSS) {
        float lsum = 0.f;
#pragma unroll
        for (int i = 0; i < TM; i++) {
            const int r = bm + trow + i;
            const int b = r >> 5;
            const float wt = wts[r];
#pragma unroll
            for (int j = 0; j < TN; j++) {
                const int c = bn + tcol + j;
                const float diff = xnn[(size_t)r * N + c]
                                 - recon[(size_t)b * N + c]
                                 - acc[i][j];
                lsum += wt * diff * diff;
            }
        }
        red[tid] = lsum;
        __syncthreads();
        for (int s = 128; s > 0; s >>= 1) {
            if (tid < s) red[tid] += red[tid + s];
            __syncthreads();
        }
        if (tid == 0) atomicAdd(lossAcc, red[0]);
    } else {
#pragma unroll
        for (int i = 0; i < TM; i++) {
            const int r = bm + trow + i;
#pragma unroll
            for (int j = 0; j < TN; j++) {
                const int c = bn + tcol + j;
                float v = acc[i][j];
                if (EPI == EPI_BIAS_RELU) { v += bias[c]; v = v > 0.f ? v : 0.f; }
                else if (EPI == EPI_BIAS) { v += bias[c]; }
                else { /* EPI_MASK */
                    v = (maskSrc[(size_t)(r >> 5) * N + c] > 0.f) ? v : 0.f;
                }
                C[(size_t)r * N + c] = v;
            }
        }
    }
}

// C(M,32) = A(M,K) @ B(K,32) + bias.  256 thr = 8 rows x 32 cols.  M%8==0, K%4==0.
__global__ void gemm_n32_k(const float* __restrict__ A, const float* __restrict__ B,
                           const float* __restrict__ bias, float* __restrict__ C,
                           int K)
{
    const int col = threadIdx.x & 31;
    const int row = blockIdx.x * 8 + (threadIdx.x >> 5);
    float s = bias[col];
    const float* a = A + (size_t)row * K;
    for (int k = 0; k < K; k += 4) {
        float4 av = *(const float4*)(a + k);
        s = fmaf(av.x, B[(k + 0) * 32 + col], s);
        s = fmaf(av.y, B[(k + 1) * 32 + col], s);
        s = fmaf(av.z, B[(k + 2) * 32 + col], s);
        s = fmaf(av.w, B[(k + 3) * 32 + col], s);
    }
    C[(size_t)row * 32 + col] = s;
}

// dz[r, j] = Zn[r, j] - Zc[r>>5, j]
__global__ void dz_k(const float* __restrict__ Zn, const float* __restrict__ Zc,
                     float* __restrict__ dz)
{
    const int idx = blockIdx.x * 256 + threadIdx.x;   // < RTOT*Z_DIM
    const int r = idx >> 5;
    const int j = idx & 31;
    dz[idx] = Zn[idx] - Zc[(r >> 5) * Z_DIM + j];
}

// binary kernel weight per neighbor row
__global__ void weights_k(const float* __restrict__ xc, const float* __restrict__ xnn,
                          float* __restrict__ w)
{
    const int r = blockIdx.x;
    const int b = r >> 5;
    const float* xcp = xc + (size_t)b * D_DIM;
    const float* xnp = xnn + (size_t)r * D_DIM;
    float s = 0.f;
    for (int d = threadIdx.x; d < D_DIM; d += 256) {
        const float df = xcp[d] - xnp[d];
        s += df * df;
    }
    __shared__ float red[256];
    red[threadIdx.x] = s;
    __syncthreads();
    for (int k = 128; k > 0; k >>= 1) {
        if (threadIdx.x < k) red[threadIdx.x] += red[threadIdx.x + k];
        __syncthreads();
    }
    if (threadIdx.x == 0) w[r] = (sqrtf(red[0]) > 1e-12f) ? 1.0f : 0.5f;
}

__global__ void zero_k(float* loss) { *loss = 0.f; }
__global__ void final_k(const float* loss, float* out) { out[0] = *loss * (1.0f / (float)RTOT); }

// ---------------------------------------------------------------------------

extern "C" void kernel_launch(void* const* d_in, const int* in_sizes, int n_in,
                              void* d_out, int out_size)
{
    (void)in_sizes; (void)n_in; (void)out_size;
    const float* x_c  = (const float*)d_in[0];
    const float* x_nn = (const float*)d_in[1];
    const float* We1  = (const float*)d_in[2];
    const float* be1  = (const float*)d_in[3];
    const float* We2  = (const float*)d_in[4];
    const float* be2  = (const float*)d_in[5];
    const float* We3  = (const float*)d_in[6];
    const float* be3  = (const float*)d_in[7];
    const float* Wd1  = (const float*)d_in[8];
    const float* bd1  = (const float*)d_in[9];
    const float* Wd2  = (const float*)d_in[10];
    const float* bd2  = (const float*)d_in[11];
    const float* Wd3  = (const float*)d_in[12];
    const float* bd3  = (const float*)d_in[13];
    float* out = (float*)d_out;

    float *H1, *H2, *H1c, *H2c, *Zn, *Zc, *h1d, *h2d, *recon, *dz, *t1, *t2, *w, *loss;
    cudaGetSymbolAddress((void**)&H1,    g_H1);
    cudaGetSymbolAddress((void**)&H2,    g_H2);
    cudaGetSymbolAddress((void**)&H1c,   g_H1c);
    cudaGetSymbolAddress((void**)&H2c,   g_H2c);
    cudaGetSymbolAddress((void**)&Zn,    g_Zn);
    cudaGetSymbolAddress((void**)&Zc,    g_Zc);
    cudaGetSymbolAddress((void**)&h1d,   g_h1d);
    cudaGetSymbolAddress((void**)&h2d,   g_h2d);
    cudaGetSymbolAddress((void**)&recon, g_recon);
    cudaGetSymbolAddress((void**)&dz,    g_dz);
    cudaGetSymbolAddress((void**)&t1,    g_t1);
    cudaGetSymbolAddress((void**)&t2,    g_t2);
    cudaGetSymbolAddress((void**)&w,     g_w);
    cudaGetSymbolAddress((void**)&loss,  g_loss);

    const dim3 blk(256);
    auto grd = [](int M, int N) { return dim3(N / BN, M / BM); };

    // encoder on x_nn (4096 rows)
    sgemm_k<EPI_BIAS_RELU><<<grd(RTOT, H_DIM), blk>>>(x_nn, We1, H1, RTOT, H_DIM, D_DIM,
                                                      be1, nullptr, nullptr, nullptr, nullptr, nullptr);
    sgemm_k<EPI_BIAS_RELU><<<grd(RTOT, H_DIM), blk>>>(H1, We2, H2, RTOT, H_DIM, H_DIM,
                                                      be2, nullptr, nullptr, nullptr, nullptr, nullptr);
    gemm_n32_k<<<RTOT / 8, blk>>>(H2, We3, be3, Zn, H_DIM);

    // encoder on x_c (128 rows)
    sgemm_k<EPI_BIAS_RELU><<<grd(BS, H_DIM), blk>>>(x_c, We1, H1c, BS, H_DIM, D_DIM,
                                                    be1, nullptr, nullptr, nullptr, nullptr, nullptr);
    sgemm_k<EPI_BIAS_RELU><<<grd(BS, H_DIM), blk>>>(H1c, We2, H2c, BS, H_DIM, H_DIM,
                                                    be2, nullptr, nullptr, nullptr, nullptr, nullptr);
    gemm_n32_k<<<BS / 8, blk>>>(H2c, We3, be3, Zc, H_DIM);

    // decoder on z_c (gives recon + ReLU masks h1d/h2d)
    sgemm_k<EPI_BIAS_RELU><<<grd(BS, H_DIM), blk>>>(Zc, Wd1, h1d, BS, H_DIM, Z_DIM,
                                                    bd1, nullptr, nullptr, nullptr, nullptr, nullptr);
    sgemm_k<EPI_BIAS_RELU><<<grd(BS, H_DIM), blk>>>(h1d, Wd2, h2d, BS, H_DIM, H_DIM,
                                                    bd2, nullptr, nullptr, nullptr, nullptr, nullptr);
    sgemm_k<EPI_BIAS><<<grd(BS, D_DIM), blk>>>(h2d, Wd3, recon, BS, D_DIM, H_DIM,
                                               bd3, nullptr, nullptr, nullptr, nullptr, nullptr);

    // tangents + kernel weights
    dz_k<<<(RTOT * Z_DIM) / 256, blk>>>(Zn, Zc, dz);
    weights_k<<<RTOT, blk>>>(x_c, x_nn, w);
    zero_k<<<1, 1>>>(loss);

    // JVP chain (hess == 0 exactly for ReLU MLP)
    sgemm_k<EPI_MASK><<<grd(RTOT, H_DIM), blk>>>(dz, Wd1, t1, RTOT, H_DIM, Z_DIM,
                                                 nullptr, h1d, nullptr, nullptr, nullptr, nullptr);
    sgemm_k<EPI_MASK><<<grd(RTOT, H_DIM), blk>>>(t1, Wd2, t2, RTOT, H_DIM, H_DIM,
                                                 nullptr, h2d, nullptr, nullptr, nullptr, nullptr);
    // final GEMM with fused weighted squared-error reduction (jac never stored)
    sgemm_k<EPI_LOSS><<<grd(RTOT, D_DIM), blk>>>(t2, Wd3, nullptr, RTOT, D_DIM, H_DIM,
                                                 nullptr, nullptr, x_nn, recon, w, loss);

    final_k<<<1, 1>>>(loss, out);
}

// round 3
// speedup vs baseline: 6.3456x; 6.3456x over previous
#include <cuda_runtime.h>
#include <cuda_bf16.h>
#include <math.h>

typedef __nv_bfloat16 bf16;

#define D_DIM 3072
#define H_DIM 1024
#define Z_DIM 32
#define BS    128
#define NN    32
#define RTOT  (BS*NN)          // 4096
#define MENC  (RTOT + BS)      // 4224 rows: x_nn followed by x_c

// smem row strides (bf16 elements), padded for conflict-free ldmatrix
#define SA 40    // 80B  (16B-aligned, odd multiple of 16B)
#define SB 136   // 272B

enum { EPI_BIAS_RELU_BF = 0, EPI_BIAS_F32 = 1, EPI_MASK_BF = 2, EPI_LOSS = 3 };

// ------------------------- scratch (no allocation) -------------------------
__device__ bf16  g_Abf  [MENC * D_DIM];      // x_nn ++ x_c in bf16
__device__ bf16  g_We1b [D_DIM * H_DIM];
__device__ bf16  g_We2b [H_DIM * H_DIM];
__device__ bf16  g_We3b [H_DIM * Z_DIM];
__device__ bf16  g_Wd1b [Z_DIM * H_DIM];
__device__ bf16  g_Wd2b [H_DIM * H_DIM];
__device__ bf16  g_Wd3b [H_DIM * D_DIM];
__device__ bf16  g_H1b  [MENC * H_DIM];
__device__ bf16  g_H2b  [MENC * H_DIM];
__device__ float g_Z    [MENC * Z_DIM];      // fp32 latents (z_nn ++ z_c)
__device__ bf16  g_dzb  [RTOT * Z_DIM];
__device__ bf16  g_zcb  [BS * Z_DIM];
__device__ bf16  g_h1db [BS * H_DIM];
__device__ bf16  g_h2db [BS * H_DIM];
__device__ float g_recon[BS * D_DIM];
__device__ bf16  g_t1b  [RTOT * H_DIM];
__device__ bf16  g_t2b  [RTOT * H_DIM];
__device__ float g_w    [RTOT];
__device__ float g_loss;

__device__ __forceinline__ unsigned smem_u32(const void* p) {
    return (unsigned)__cvta_generic_to_shared(p);
}

// ---------------------------------------------------------------------------
// bf16 tensor-core GEMM: C(M,N) = epi(A(M,K) @ B(K,N)), fp32 accumulate.
// Block tile 128x128, K-chunk 32, 8 warps (2x4), warp tile 64x32.
// M%128==0, N%128==0, K%32==0.
// ---------------------------------------------------------------------------
template<int EPI>
__global__ __launch_bounds__(256)
void mma_gemm(const bf16* __restrict__ A, const bf16* __restrict__ B,
              void* __restrict__ Cout, int M, int N, int K,
              const float* __restrict__ bias,
              const bf16* __restrict__ maskSrc,     // [M/32, N] for EPI_MASK
              const float* __restrict__ xnn,        // [M, N] for EPI_LOSS
              const float* __restrict__ recon,      // [M/32, N] for EPI_LOSS
              const float* __restrict__ wts,        // [M] for EPI_LOSS
              float* __restrict__ lossAcc)
{
    __shared__ __align__(16) bf16 Asm[2][128 * SA];
    __shared__ __align__(16) bf16 Bsm[2][32 * SB];
    __shared__ float red[256];

    const int tid  = threadIdx.x;
    const int lane = tid & 31;
    const int wid  = tid >> 5;
    const int bm = blockIdx.y * 128;
    const int bn = blockIdx.x * 128;
    const int warpM = (wid >> 2) * 64;
    const int warpN = (wid & 3) * 32;

    // global->smem load mapping (16B chunks)
    const int ar = tid >> 2;            // A row 0..63 (+64 second)
    const int ac = (tid & 3) * 8;       // A col chunk
    const int br = tid >> 3;            // B row 0..31
    const int bc = (tid & 7) * 8;       // B col chunk (+64 second)

    const bf16* Ag  = A + (size_t)(bm + ar) * K + ac;
    const bf16* Ag2 = Ag + (size_t)64 * K;
    const bf16* Bg  = B + (size_t)br * N + bn + bc;

    const unsigned sA0 = smem_u32(&Asm[0][ar * SA + ac]);
    const unsigned sA1 = smem_u32(&Asm[0][(ar + 64) * SA + ac]);
    const unsigned sB0 = smem_u32(&Bsm[0][br * SB + bc]);
    const unsigned sB1 = smem_u32(&Bsm[0][br * SB + bc + 64]);
    const unsigned stgA = (unsigned)(128 * SA * 2);
    const unsigned stgB = (unsigned)(32 * SB * 2);

    float acc[4][4][4];
#pragma unroll
    for (int i = 0; i < 4; i++)
#pragma unroll
        for (int j = 0; j < 4; j++)
#pragma unroll
            for (int q = 0; q < 4; q++) acc[i][j][q] = 0.f;

    const int KT = K / 32;

#define LOAD_STAGE(s, kt)                                                        \
    do {                                                                         \
        const bf16* ga  = Ag  + (size_t)(kt) * 32;                               \
        const bf16* ga2 = Ag2 + (size_t)(kt) * 32;                               \
        const bf16* gb  = Bg  + (size_t)(kt) * 32 * N;                           \
        asm volatile("cp.async.cg.shared.global [%0], [%1], 16;\n"               \
                     "cp.async.cg.shared.global [%2], [%3], 16;\n"               \
                     "cp.async.cg.shared.global [%4], [%5], 16;\n"               \
                     "cp.async.cg.shared.global [%6], [%7], 16;\n"               \
                     :: "r"(sA0 + (s) * stgA), "l"(ga),                          \
                        "r"(sA1 + (s) * stgA), "l"(ga2),                         \
                        "r"(sB0 + (s) * stgB), "l"(gb),                          \
                        "r"(sB1 + (s) * stgB), "l"(gb + 64));                    \
        asm volatile("cp.async.commit_group;\n");                                \
    } while (0)

    LOAD_STAGE(0, 0);

    for (int kt = 0; kt < KT; kt++) {
        const int s = kt & 1;
        if (kt + 1 < KT) {
            LOAD_STAGE(s ^ 1, kt + 1);
            asm volatile("cp.async.wait_group 1;\n");
        } else {
            asm volatile("cp.async.wait_group 0;\n");
        }
        __syncthreads();

        const unsigned abase = smem_u32(&Asm[s][0]);
        const unsigned bbase = smem_u32(&Bsm[s][0]);
#pragma unroll
        for (int ks = 0; ks < 32; ks += 16) {
            unsigned a[4][4];
#pragma unroll
            for (int ms = 0; ms < 4; ms++) {
                unsigned addr = abase +
                    ((warpM + ms * 16 + (lane & 15)) * SA + ks + (lane >> 4) * 8) * 2;
                asm volatile("ldmatrix.sync.aligned.m8n8.x4.shared.b16 {%0,%1,%2,%3}, [%4];"
                             : "=r"(a[ms][0]), "=r"(a[ms][1]), "=r"(a[ms][2]), "=r"(a[ms][3])
                             : "r"(addr));
            }
            unsigned b[4][2];
#pragma unroll
            for (int np = 0; np < 2; np++) {
                unsigned addr = bbase +
                    ((ks + (lane & 15)) * SB + warpN + np * 16 + (lane >> 4) * 8) * 2;
                unsigned r0, r1, r2, r3;
                asm volatile("ldmatrix.sync.aligned.m8n8.x4.trans.shared.b16 {%0,%1,%2,%3}, [%4];"
                             : "=r"(r0), "=r"(r1), "=r"(r2), "=r"(r3) : "r"(addr));
                b[np * 2][0] = r0; b[np * 2][1] = r1;
                b[np * 2 + 1][0] = r2; b[np * 2 + 1][1] = r3;
            }
#pragma unroll
            for (int ms = 0; ms < 4; ms++)
#pragma unroll
                for (int ns = 0; ns < 4; ns++)
                    asm volatile(
                        "mma.sync.aligned.m16n8k16.row.col.f32.bf16.bf16.f32 "
                        "{%0,%1,%2,%3}, {%4,%5,%6,%7}, {%8,%9}, {%0,%1,%2,%3};"
                        : "+f"(acc[ms][ns][0]), "+f"(acc[ms][ns][1]),
                          "+f"(acc[ms][ns][2]), "+f"(acc[ms][ns][3])
                        : "r"(a[ms][0]), "r"(a[ms][1]), "r"(a[ms][2]), "r"(a[ms][3]),
                          "r"(b[ns][0]), "r"(b[ns][1]));
        }
        __syncthreads();
    }
#undef LOAD_STAGE

    // ------------------------------ epilogue ------------------------------
    // c frag: rows r0 = bm+warpM+ms*16+(lane>>2), r1 = r0+8;
    //         cols c = bn+warpN+ns*8+(lane&3)*2, c+1
    if (EPI == EPI_LOSS) {
        float lsum = 0.f;
#pragma unroll
        for (int ms = 0; ms < 4; ms++) {
            const int r0 = bm + warpM + ms * 16 + (lane >> 2);
            const int r1 = r0 + 8;
            const float w0 = wts[r0], w1 = wts[r1];
            const int b0 = r0 >> 5, b1 = r1 >> 5;
#pragma unroll
            for (int ns = 0; ns < 4; ns++) {
                const int c = bn + warpN + ns * 8 + (lane & 3) * 2;
                float2 x0 = *(const float2*)(xnn + (size_t)r0 * N + c);
                float2 x1 = *(const float2*)(xnn + (size_t)r1 * N + c);
                float2 rc0 = *(const float2*)(recon + (size_t)b0 * N + c);
                float2 rc1 = *(const float2*)(recon + (size_t)b1 * N + c);
                float d0 = x0.x - rc0.x - acc[ms][ns][0];
                float d1 = x0.y - rc0.y - acc[ms][ns][1];
                float d2 = x1.x - rc1.x - acc[ms][ns][2];
                float d3 = x1.y - rc1.y - acc[ms][ns][3];
                lsum += w0 * (d0 * d0 + d1 * d1) + w1 * (d2 * d2 + d3 * d3);
            }
        }
        red[tid] = lsum;
        __syncthreads();
        for (int s2 = 128; s2 > 0; s2 >>= 1) {
            if (tid < s2) red[tid] += red[tid + s2];
            __syncthreads();
        }
        if (tid == 0) atomicAdd(lossAcc, red[0]);
    } else {
#pragma unroll
        for (int ms = 0; ms < 4; ms++) {
            const int r0 = bm + warpM + ms * 16 + (lane >> 2);
            const int r1 = r0 + 8;
#pragma unroll
            for (int ns = 0; ns < 4; ns++) {
                const int c = bn + warpN + ns * 8 + (lane & 3) * 2;
                float v0 = acc[ms][ns][0], v1 = acc[ms][ns][1];
                float v2 = acc[ms][ns][2], v3 = acc[ms][ns][3];
                if (EPI == EPI_BIAS_RELU_BF) {
                    const float b_0 = bias[c], b_1 = bias[c + 1];
                    v0 = fmaxf(v0 + b_0, 0.f); v1 = fmaxf(v1 + b_1, 0.f);
                    v2 = fmaxf(v2 + b_0, 0.f); v3 = fmaxf(v3 + b_1, 0.f);
                    bf16* C = (bf16*)Cout;
                    *(__nv_bfloat162*)(C + (size_t)r0 * N + c) =
                        __floats2bfloat162_rn(v0, v1);
                    *(__nv_bfloat162*)(C + (size_t)r1 * N + c) =
                        __floats2bfloat162_rn(v2, v3);
                } else if (EPI == EPI_BIAS_F32) {
                    const float b_0 = bias[c], b_1 = bias[c + 1];
                    float* C = (float*)Cout;
                    *(float2*)(C + (size_t)r0 * N + c) = make_float2(v0 + b_0, v1 + b_1);
                    *(float2*)(C + (size_t)r1 * N + c) = make_float2(v2 + b_0, v3 + b_1);
                } else { // EPI_MASK_BF
                    const __nv_bfloat162 m0 =
                        *(const __nv_bfloat162*)(maskSrc + (size_t)(r0 >> 5) * N + c);
                    const __nv_bfloat162 m1 =
                        *(const __nv_bfloat162*)(maskSrc + (size_t)(r1 >> 5) * N + c);
                    v0 = (__bfloat162float(m0.x) > 0.f) ? v0 : 0.f;
                    v1 = (__bfloat162float(m0.y) > 0.f) ? v1 : 0.f;
                    v2 = (__bfloat162float(m1.x) > 0.f) ? v2 : 0.f;
                    v3 = (__bfloat162float(m1.y) > 0.f) ? v3 : 0.f;
                    bf16* C = (bf16*)Cout;
                    *(__nv_bfloat162*)(C + (size_t)r0 * N + c) =
                        __floats2bfloat162_rn(v0, v1);
                    *(__nv_bfloat162*)(C + (size_t)r1 * N + c) =
                        __floats2bfloat162_rn(v2, v3);
                }
            }
        }
    }
}

// ---------------------------------------------------------------------------
// small GEMM, N=32 (latent projection): C(M,32) = A(M,K)@B(K,32) + bias, fp32 out
// ---------------------------------------------------------------------------
__global__ void gemm_n32_bf(const bf16* __restrict__ A, const bf16* __restrict__ B,
                            const float* __restrict__ bias, float* __restrict__ C,
                            int K)
{
    const int col = threadIdx.x & 31;
    const int row = blockIdx.x * 8 + (threadIdx.x >> 5);
    const bf16* a = A + (size_t)row * K;
    float s = bias[col];
    for (int k = 0; k < K; k += 8) {
        uint4 raw = *(const uint4*)(a + k);
        const __nv_bfloat162* av = (const __nv_bfloat162*)&raw;
#pragma unroll
        for (int i = 0; i < 4; i++) {
            float2 f = __bfloat1622float2(av[i]);
            s = fmaf(f.x, __bfloat162float(B[(k + 2 * i) * 32 + col]), s);
            s = fmaf(f.y, __bfloat162float(B[(k + 2 * i + 1) * 32 + col]), s);
        }
    }
    C[(size_t)row * 32 + col] = s;
}

// fp32 -> bf16 conversion (n % 4 == 0)
__global__ void f2bf_k(const float* __restrict__ in, bf16* __restrict__ out, int n)
{
    int i = (blockIdx.x * 256 + threadIdx.x) * 4;
    if (i < n) {
        float4 v = *(const float4*)(in + i);
        *(__nv_bfloat162*)(out + i)     = __floats2bfloat162_rn(v.x, v.y);
        *(__nv_bfloat162*)(out + i + 2) = __floats2bfloat162_rn(v.z, v.w);
    }
}

// dz (bf16) = z_nn - z_c, plus z_c -> bf16
__global__ void dz_k(const float* __restrict__ Z, bf16* __restrict__ dzb,
                     bf16* __restrict__ zcb)
{
    const int idx = blockIdx.x * 256 + threadIdx.x;
    if (idx < RTOT * Z_DIM) {
        const int r = idx >> 5, j = idx & 31, b = r >> 5;
        dzb[idx] = __float2bfloat16(Z[idx] - Z[(RTOT + b) * Z_DIM + j]);
    } else if (idx < RTOT * Z_DIM + BS * Z_DIM) {
        const int k = idx - RTOT * Z_DIM;
        zcb[k] = __float2bfloat16(Z[RTOT * Z_DIM + k]);
    }
}

// binary kernel weights (fp32 inputs)
__global__ void weights_k(const float* __restrict__ xc, const float* __restrict__ xnn,
                          float* __restrict__ w)
{
    const int r = blockIdx.x;
    const int b = r >> 5;
    const float* xcp = xc + (size_t)b * D_DIM;
    const float* xnp = xnn + (size_t)r * D_DIM;
    float s = 0.f;
    for (int d = threadIdx.x; d < D_DIM; d += 256) {
        const float df = xcp[d] - xnp[d];
        s += df * df;
    }
    __shared__ float red[256];
    red[threadIdx.x] = s;
    __syncthreads();
    for (int k = 128; k > 0; k >>= 1) {
        if (threadIdx.x < k) red[threadIdx.x] += red[threadIdx.x + k];
        __syncthreads();
    }
    if (threadIdx.x == 0) w[r] = (sqrtf(red[0]) > 1e-12f) ? 1.0f : 0.5f;
}

__global__ void zero_k(float* loss) { *loss = 0.f; }
__global__ void final_k(const float* loss, float* out) { out[0] = *loss * (1.0f / (float)RTOT); }

// ---------------------------------------------------------------------------

extern "C" void kernel_launch(void* const* d_in, const int* in_sizes, int n_in,
                              void* d_out, int out_size)
{
    (void)in_sizes; (void)n_in; (void)out_size;
    const float* x_c  = (const float*)d_in[0];
    const float* x_nn = (const float*)d_in[1];
    const float* We1  = (const float*)d_in[2];
    const float* be1  = (const float*)d_in[3];
    const float* We2  = (const float*)d_in[4];
    const float* be2  = (const float*)d_in[5];
    const float* We3  = (const float*)d_in[6];
    const float* be3  = (const float*)d_in[7];
    const float* Wd1  = (const float*)d_in[8];
    const float* bd1  = (const float*)d_in[9];
    const float* Wd2  = (const float*)d_in[10];
    const float* bd2  = (const float*)d_in[11];
    const float* Wd3  = (const float*)d_in[12];
    const float* bd3  = (const float*)d_in[13];
    float* out = (float*)d_out;

    bf16 *Abf, *We1b, *We2b, *We3b, *Wd1b, *Wd2b, *Wd3b;
    bf16 *H1b, *H2b, *dzb, *zcb, *h1db, *h2db, *t1b, *t2b;
    float *Z, *recon, *w, *loss;
    cudaGetSymbolAddress((void**)&Abf,   g_Abf);
    cudaGetSymbolAddress((void**)&We1b,  g_We1b);
    cudaGetSymbolAddress((void**)&We2b,  g_We2b);
    cudaGetSymbolAddress((void**)&We3b,  g_We3b);
    cudaGetSymbolAddress((void**)&Wd1b,  g_Wd1b);
    cudaGetSymbolAddress((void**)&Wd2b,  g_Wd2b);
    cudaGetSymbolAddress((void**)&Wd3b,  g_Wd3b);
    cudaGetSymbolAddress((void**)&H1b,   g_H1b);
    cudaGetSymbolAddress((void**)&H2b,   g_H2b);
    cudaGetSymbolAddress((void**)&Z,     g_Z);
    cudaGetSymbolAddress((void**)&dzb,   g_dzb);
    cudaGetSymbolAddress((void**)&zcb,   g_zcb);
    cudaGetSymbolAddress((void**)&h1db,  g_h1db);
    cudaGetSymbolAddress((void**)&h2db,  g_h2db);
    cudaGetSymbolAddress((void**)&recon, g_recon);
    cudaGetSymbolAddress((void**)&t1b,   g_t1b);
    cudaGetSymbolAddress((void**)&t2b,   g_t2b);
    cudaGetSymbolAddress((void**)&w,     g_w);
    cudaGetSymbolAddress((void**)&loss,  g_loss);

    const dim3 blk(256);
    auto cgrid = [](int n) { return dim3((n / 4 + 255) / 256); };
    auto ggrid = [](int M, int N) { return dim3(N / 128, M / 128); };

    // conversions to bf16
    f2bf_k<<<cgrid(RTOT * D_DIM), blk>>>(x_nn, Abf, RTOT * D_DIM);
    f2bf_k<<<cgrid(BS * D_DIM), blk>>>(x_c, Abf + (size_t)RTOT * D_DIM, BS * D_DIM);
    f2bf_k<<<cgrid(D_DIM * H_DIM), blk>>>(We1, We1b, D_DIM * H_DIM);
    f2bf_k<<<cgrid(H_DIM * H_DIM), blk>>>(We2, We2b, H_DIM * H_DIM);
    f2bf_k<<<cgrid(H_DIM * Z_DIM), blk>>>(We3, We3b, H_DIM * Z_DIM);
    f2bf_k<<<cgrid(Z_DIM * H_DIM), blk>>>(Wd1, Wd1b, Z_DIM * H_DIM);
    f2bf_k<<<cgrid(H_DIM * H_DIM), blk>>>(Wd2, Wd2b, H_DIM * H_DIM);
    f2bf_k<<<cgrid(H_DIM * D_DIM), blk>>>(Wd3, Wd3b, H_DIM * D_DIM);

    // encoder (x_nn ++ x_c merged, M = 4224)
    mma_gemm<EPI_BIAS_RELU_BF><<<ggrid(MENC, H_DIM), blk>>>(
        Abf, We1b, H1b, MENC, H_DIM, D_DIM, be1, nullptr, nullptr, nullptr, nullptr, nullptr);
    mma_gemm<EPI_BIAS_RELU_BF><<<ggrid(MENC, H_DIM), blk>>>(
        H1b, We2b, H2b, MENC, H_DIM, H_DIM, be2, nullptr, nullptr, nullptr, nullptr, nullptr);
    gemm_n32_bf<<<MENC / 8, blk>>>(H2b, We3b, be3, Z, H_DIM);

    // tangents, weights, loss init
    dz_k<<<(RTOT * Z_DIM + BS * Z_DIM) / 256, blk>>>(Z, dzb, zcb);
    weights_k<<<RTOT, blk>>>(x_c, x_nn, w);
    zero_k<<<1, 1>>>(loss);

    // decoder at z_c: activations (ReLU masks) + recon
    mma_gemm<EPI_BIAS_RELU_BF><<<ggrid(BS, H_DIM), blk>>>(
        zcb, Wd1b, h1db, BS, H_DIM, Z_DIM, bd1, nullptr, nullptr, nullptr, nullptr, nullptr);
    mma_gemm<EPI_BIAS_RELU_BF><<<ggrid(BS, H_DIM), blk>>>(
        h1db, Wd2b, h2db, BS, H_DIM, H_DIM, bd2, nullptr, nullptr, nullptr, nullptr, nullptr);
    mma_gemm<EPI_BIAS_F32><<<ggrid(BS, D_DIM), blk>>>(
        h2db, Wd3b, recon, BS, D_DIM, H_DIM, bd3, nullptr, nullptr, nullptr, nullptr, nullptr);

    // JVP chain (hess == 0 exactly for ReLU MLP)
    mma_gemm<EPI_MASK_BF><<<ggrid(RTOT, H_DIM), blk>>>(
        dzb, Wd1b, t1b, RTOT, H_DIM, Z_DIM, nullptr, h1db, nullptr, nullptr, nullptr, nullptr);
    mma_gemm<EPI_MASK_BF><<<ggrid(RTOT, H_DIM), blk>>>(
        t1b, Wd2b, t2b, RTOT, H_DIM, H_DIM, nullptr, h2db, nullptr, nullptr, nullptr, nullptr);
    // final GEMM with fused weighted squared-error reduction (jac never stored)
    mma_gemm<EPI_LOSS><<<ggrid(RTOT, D_DIM), blk>>>(
        t2b, Wd3b, nullptr, RTOT, D_DIM, H_DIM, nullptr, nullptr, x_nn, recon, w, loss);

    final_k<<<1, 1>>>(loss, out);
}

// round 5
// speedup vs baseline: 7.2727x; 1.1461x over previous
#include <cuda_runtime.h>
#include <cuda_bf16.h>
#include <cstdint>
#include <math.h>

typedef __nv_bfloat16 bf16;

#define D_DIM 3072
#define H_DIM 1024
#define Z_DIM 32
#define BS    128
#define NN    32
#define RTOT  4096
#define MENC  4224

// smem row strides (bf16 elements), padded for conflict-free ldmatrix
#define SA 40    // A tile row stride (80B)
#define SB 136   // B tile row stride (272B)

#define ASZ (128 * SA * 2)          // bytes per A stage
#define BSZ (32 * SB * 2)           // bytes per B stage
#define STG (ASZ + BSZ)             // bytes per stage
#define NSTAGE 3
#define SMEM_DYN (NSTAGE * STG)

enum { EPI_BIAS_RELU_BF = 0, EPI_BIAS_F32 = 1, EPI_MASK_BF = 2, EPI_LOSS = 3 };

// ------------------------- scratch (no allocation) -------------------------
__device__ __align__(16) bf16  g_Abf  [MENC * D_DIM];      // x_nn ++ x_c in bf16
__device__ __align__(16) bf16  g_We1b [D_DIM * H_DIM];
__device__ __align__(16) bf16  g_We2b [H_DIM * H_DIM];
__device__ __align__(16) bf16  g_We3b [H_DIM * Z_DIM];
__device__ __align__(16) bf16  g_Wd1b [Z_DIM * H_DIM];
__device__ __align__(16) bf16  g_Wd2b [H_DIM * H_DIM];
__device__ __align__(16) bf16  g_Wd3b [H_DIM * D_DIM];
__device__ __align__(16) bf16  g_H1b  [MENC * H_DIM];
__device__ __align__(16) bf16  g_H2b  [MENC * H_DIM];
__device__ __align__(16) float g_Z    [MENC * Z_DIM];      // fp32 latents
__device__ __align__(16) bf16  g_dzb  [RTOT * Z_DIM];
__device__ __align__(16) bf16  g_zcb  [BS * Z_DIM];
__device__ __align__(16) bf16  g_h1db [BS * H_DIM];
__device__ __align__(16) bf16  g_h2db [BS * H_DIM];
__device__ __align__(16) float g_recon[BS * D_DIM];
__device__ __align__(16) bf16  g_t1b  [RTOT * H_DIM];
__device__ __align__(16) bf16  g_t2b  [RTOT * H_DIM];
__device__ float g_w[RTOT];
__device__ float g_loss;

__device__ __forceinline__ unsigned smem_u32(const void* p) {
    return (unsigned)__cvta_generic_to_shared(p);
}
__device__ __forceinline__ void cpasync16(unsigned dst, const void* src) {
    asm volatile("cp.async.cg.shared.global [%0], [%1], 16;" :: "r"(dst), "l"(src));
}

// ---------------------------------------------------------------------------
// bf16 tensor-core GEMM: C(M,N) = epi(A(M,K) @ B(K,N)), fp32 accumulate.
// Block tile 128x128, K-chunk 32, 3-stage cp.async pipeline, 8 warps (2x4),
// warp tile 64x32.  M%128==0, N%128==0, K%32==0.
// ---------------------------------------------------------------------------
template<int EPI>
__global__ __launch_bounds__(256, 2)
void mma_gemm(const bf16* __restrict__ A, const bf16* __restrict__ B,
              void* __restrict__ Cout, int M, int N, int K,
              const float* __restrict__ bias,
              const bf16* __restrict__ maskSrc,     // [M/32, N] for EPI_MASK
              const float* __restrict__ xnn,        // [M, N] for EPI_LOSS
              const float* __restrict__ recon,      // [M/32, N] for EPI_LOSS
              const float* __restrict__ wts,        // [M] for EPI_LOSS
              float* __restrict__ lossAcc)
{
    extern __shared__ __align__(16) char dsm[];
    __shared__ float red[256];

    const int tid  = threadIdx.x;
    const int lane = tid & 31;
    const int wid  = tid >> 5;
    const int bm = blockIdx.y * 128;
    const int bn = blockIdx.x * 128;
    const int warpM = (wid >> 2) * 64;
    const int warpN = (wid & 3) * 32;

    // global->smem load mapping (16B chunks)
    const int ar = tid >> 2;            // A row 0..63 (+64 second)
    const int ac = (tid & 3) * 8;       // A col chunk
    const int br = tid >> 3;            // B row 0..31
    const int bc = (tid & 7) * 8;       // B col chunk (+64 second)

    const bf16* Ag  = A + (size_t)(bm + ar) * K + ac;
    const bf16* Ag2 = Ag + (size_t)64 * K;
    const bf16* Bg  = B + (size_t)br * N + bn + bc;

    const unsigned dyn0 = smem_u32(dsm);
    const unsigned oA0 = (unsigned)((ar * SA + ac) * 2);
    const unsigned oA1 = (unsigned)(((ar + 64) * SA + ac) * 2);
    const unsigned oB0 = (unsigned)(ASZ + (br * SB + bc) * 2);
    const unsigned oB1 = (unsigned)(ASZ + (br * SB + bc + 64) * 2);

    float acc[4][4][4];
#pragma unroll
    for (int i = 0; i < 4; i++)
#pragma unroll
        for (int j = 0; j < 4; j++)
#pragma unroll
            for (int q = 0; q < 4; q++) acc[i][j][q] = 0.f;

    const int KT = K / 32;

    auto load_tile = [&](int kt) {
        if (kt < KT) {
            const unsigned base = dyn0 + (kt % NSTAGE) * STG;
            const bf16* ga  = Ag  + (size_t)kt * 32;
            const bf16* ga2 = Ag2 + (size_t)kt * 32;
            const bf16* gb  = Bg  + (size_t)kt * 32 * N;
            cpasync16(base + oA0, ga);
            cpasync16(base + oA1, ga2);
            cpasync16(base + oB0, gb);
            cpasync16(base + oB1, gb + 64);
        }
        asm volatile("cp.async.commit_group;" ::: "memory");
    };

    load_tile(0);
    load_tile(1);

    for (int kt = 0; kt < KT; kt++) {
        asm volatile("cp.async.wait_group 1;" ::: "memory");
        __syncthreads();
        load_tile(kt + 2);

        const unsigned base = dyn0 + (kt % NSTAGE) * STG;
        const unsigned abase = base;
        const unsigned bbase = base + ASZ;
#pragma unroll
        for (int ks = 0; ks < 32; ks += 16) {
            unsigned a[4][4];
#pragma unroll
            for (int ms = 0; ms < 4; ms++) {
                unsigned addr = abase +
                    ((warpM + ms * 16 + (lane & 15)) * SA + ks + (lane >> 4) * 8) * 2;
                asm volatile("ldmatrix.sync.aligned.m8n8.x4.shared.b16 {%0,%1,%2,%3}, [%4];"
                             : "=r"(a[ms][0]), "=r"(a[ms][1]), "=r"(a[ms][2]), "=r"(a[ms][3])
                             : "r"(addr));
            }
            unsigned b[4][2];
#pragma unroll
            for (int np = 0; np < 2; np++) {
                unsigned addr = bbase +
                    ((ks + (lane & 15)) * SB + warpN + np * 16 + (lane >> 4) * 8) * 2;
                unsigned r0, r1, r2, r3;
                asm volatile("ldmatrix.sync.aligned.m8n8.x4.trans.shared.b16 {%0,%1,%2,%3}, [%4];"
                             : "=r"(r0), "=r"(r1), "=r"(r2), "=r"(r3) : "r"(addr));
                b[np * 2][0] = r0; b[np * 2][1] = r1;
                b[np * 2 + 1][0] = r2; b[np * 2 + 1][1] = r3;
            }
#pragma unroll
            for (int ms = 0; ms < 4; ms++)
#pragma unroll
                for (int ns = 0; ns < 4; ns++)
                    asm volatile(
                        "mma.sync.aligned.m16n8k16.row.col.f32.bf16.bf16.f32 "
                        "{%0,%1,%2,%3}, {%4,%5,%6,%7}, {%8,%9}, {%0,%1,%2,%3};"
                        : "+f"(acc[ms][ns][0]), "+f"(acc[ms][ns][1]),
                          "+f"(acc[ms][ns][2]), "+f"(acc[ms][ns][3])
                        : "r"(a[ms][0]), "r"(a[ms][1]), "r"(a[ms][2]), "r"(a[ms][3]),
                          "r"(b[ns][0]), "r"(b[ns][1]));
        }
        __syncthreads();
    }

    // ------------------------------ epilogue ------------------------------
    if (EPI == EPI_LOSS) {
        float lsum = 0.f;
#pragma unroll
        for (int ms = 0; ms < 4; ms++) {
            const int r0 = bm + warpM + ms * 16 + (lane >> 2);
            const int r1 = r0 + 8;
            const float w0 = wts[r0], w1 = wts[r1];
            const int b0 = r0 >> 5, b1 = r1 >> 5;
#pragma unroll
            for (int ns = 0; ns < 4; ns++) {
                const int c = bn + warpN + ns * 8 + (lane & 3) * 2;
                float2 x0 = *(const float2*)(xnn + (size_t)r0 * N + c);
                float2 x1 = *(const float2*)(xnn + (size_t)r1 * N + c);
                float2 rc0 = *(const float2*)(recon + (size_t)b0 * N + c);
                float2 rc1 = *(const float2*)(recon + (size_t)b1 * N + c);
                float d0 = x0.x - rc0.x - acc[ms][ns][0];
                float d1 = x0.y - rc0.y - acc[ms][ns][1];
                float d2 = x1.x - rc1.x - acc[ms][ns][2];
                float d3 = x1.y - rc1.y - acc[ms][ns][3];
                lsum += w0 * (d0 * d0 + d1 * d1) + w1 * (d2 * d2 + d3 * d3);
            }
        }
        red[tid] = lsum;
        __syncthreads();
        for (int s2 = 128; s2 > 0; s2 >>= 1) {
            if (tid < s2) red[tid] += red[tid + s2];
            __syncthreads();
        }
        if (tid == 0) atomicAdd(lossAcc, red[0]);
    } else {
#pragma unroll
        for (int ms = 0; ms < 4; ms++) {
            const int r0 = bm + warpM + ms * 16 + (lane >> 2);
            const int r1 = r0 + 8;
#pragma unroll
            for (int ns = 0; ns < 4; ns++) {
                const int c = bn + warpN + ns * 8 + (lane & 3) * 2;
                float v0 = acc[ms][ns][0], v1 = acc[ms][ns][1];
                float v2 = acc[ms][ns][2], v3 = acc[ms][ns][3];
                if (EPI == EPI_BIAS_RELU_BF) {
                    const float b_0 = bias[c], b_1 = bias[c + 1];
                    v0 = fmaxf(v0 + b_0, 0.f); v1 = fmaxf(v1 + b_1, 0.f);
                    v2 = fmaxf(v2 + b_0, 0.f); v3 = fmaxf(v3 + b_1, 0.f);
                    bf16* C = (bf16*)Cout;
                    *(__nv_bfloat162*)(C + (size_t)r0 * N + c) =
                        __floats2bfloat162_rn(v0, v1);
                    *(__nv_bfloat162*)(C + (size_t)r1 * N + c) =
                        __floats2bfloat162_rn(v2, v3);
                } else if (EPI == EPI_BIAS_F32) {
                    const float b_0 = bias[c], b_1 = bias[c + 1];
                    float* C = (float*)Cout;
                    *(float2*)(C + (size_t)r0 * N + c) = make_float2(v0 + b_0, v1 + b_1);
                    *(float2*)(C + (size_t)r1 * N + c) = make_float2(v2 + b_0, v3 + b_1);
                } else { // EPI_MASK_BF
                    const __nv_bfloat162 m0 =
                        *(const __nv_bfloat162*)(maskSrc + (size_t)(r0 >> 5) * N + c);
                    const __nv_bfloat162 m1 =
                        *(const __nv_bfloat162*)(maskSrc + (size_t)(r1 >> 5) * N + c);
                    v0 = (__bfloat162float(__low2bfloat16(m0)) > 0.f) ? v0 : 0.f;
                    v1 = (__bfloat162float(__high2bfloat16(m0)) > 0.f) ? v1 : 0.f;
                    v2 = (__bfloat162float(__low2bfloat16(m1)) > 0.f) ? v2 : 0.f;
                    v3 = (__bfloat162float(__high2bfloat16(m1)) > 0.f) ? v3 : 0.f;
                    bf16* C = (bf16*)Cout;
                    *(__nv_bfloat162*)(C + (size_t)r0 * N + c) =
                        __floats2bfloat162_rn(v0, v1);
                    *(__nv_bfloat162*)(C + (size_t)r1 * N + c) =
                        __floats2bfloat162_rn(v2, v3);
                }
            }
        }
    }
}

// ---------------------------------------------------------------------------
// small GEMM, N=32 latent projection: C(M,32) = A(M,K)@B(K,32) + bias, fp32 out
// ---------------------------------------------------------------------------
__global__ void gemm_n32_bf(const bf16* __restrict__ A, const bf16* __restrict__ B,
                            const float* __restrict__ bias, float* __restrict__ C,
                            int K)
{
    const int col = threadIdx.x & 31;
    const int row = blockIdx.x * 8 + (threadIdx.x >> 5);
    const bf16* a = A + (size_t)row * K;
    float s = bias[col];
    for (int k = 0; k < K; k += 8) {
        uint4 raw = *(const uint4*)(a + k);
        const __nv_bfloat162* av = (const __nv_bfloat162*)&raw;
#pragma unroll
        for (int i = 0; i < 4; i++) {
            float2 f = __bfloat1622float2(av[i]);
            s = fmaf(f.x, __bfloat162float(B[(k + 2 * i) * 32 + col]), s);
            s = fmaf(f.y, __bfloat162float(B[(k + 2 * i + 1) * 32 + col]), s);
        }
    }
    C[(size_t)row * 32 + col] = s;
}

// fp32 -> bf16 conversion (n % 4 == 0)
__global__ void f2bf_k(const float* __restrict__ in, bf16* __restrict__ out, int n)
{
    int i = (blockIdx.x * 256 + threadIdx.x) * 4;
    if (i < n) {
        float4 v = *(const float4*)(in + i);
        *(__nv_bfloat162*)(out + i)     = __floats2bfloat162_rn(v.x, v.y);
        *(__nv_bfloat162*)(out + i + 2) = __floats2bfloat162_rn(v.z, v.w);
    }
}

// dz (bf16) = z_nn - z_c, plus z_c -> bf16
__global__ void dz_k(const float* __restrict__ Z, bf16* __restrict__ dzb,
                     bf16* __restrict__ zcb)
{
    const int idx = blockIdx.x * 256 + threadIdx.x;
    if (idx < RTOT * Z_DIM) {
        const int r = idx >> 5, j = idx & 31, b = r >> 5;
        dzb[idx] = __float2bfloat16(Z[idx] - Z[(RTOT + b) * Z_DIM + j]);
    } else if (idx < RTOT * Z_DIM + BS * Z_DIM) {
        const int k = idx - RTOT * Z_DIM;
        zcb[k] = __float2bfloat16(Z[RTOT * Z_DIM + k]);
    }
}

// binary kernel weights (fp32 inputs)
__global__ void weights_k(const float* __restrict__ xc, const float* __restrict__ xnn,
                          float* __restrict__ w)
{
    const int r = blockIdx.x;
    const float* xcp = xc + (size_t)(r >> 5) * D_DIM;
    const float* xnp = xnn + (size_t)r * D_DIM;
    float s = 0.f;
    for (int d = threadIdx.x; d < D_DIM; d += 256) {
        const float df = xcp[d] - xnp[d];
        s += df * df;
    }
    __shared__ float red[256];
    red[threadIdx.x] = s;
    __syncthreads();
    for (int k = 128; k > 0; k >>= 1) {
        if (threadIdx.x < k) red[threadIdx.x] += red[threadIdx.x + k];
        __syncthreads();
    }
    if (threadIdx.x == 0) w[r] = (sqrtf(red[0]) > 1e-12f) ? 1.0f : 0.5f;
}

__global__ void zero_k(float* loss) { *loss = 0.f; }
__global__ void final_k(const float* loss, float* out) { out[0] = *loss * (1.0f / (float)RTOT); }

// ---------------------------------------------------------------------------

extern "C" void kernel_launch(void* const* d_in, const int* in_sizes, int n_in,
                              void* d_out, int out_size)
{
    (void)in_sizes; (void)n_in; (void)out_size;
    const float* x_c  = (const float*)d_in[0];
    const float* x_nn = (const float*)d_in[1];
    const float* We1  = (const float*)d_in[2];
    const float* be1  = (const float*)d_in[3];
    const float* We2  = (const float*)d_in[4];
    const float* be2  = (const float*)d_in[5];
    const float* We3  = (const float*)d_in[6];
    const float* be3  = (const float*)d_in[7];
    const float* Wd1  = (const float*)d_in[8];
    const float* bd1  = (const float*)d_in[9];
    const float* Wd2  = (const float*)d_in[10];
    const float* bd2  = (const float*)d_in[11];
    const float* Wd3  = (const float*)d_in[12];
    const float* bd3  = (const float*)d_in[13];
    float* out = (float*)d_out;

    bf16 *Abf, *We1b, *We2b, *We3b, *Wd1b, *Wd2b, *Wd3b;
    bf16 *H1b, *H2b, *dzb, *zcb, *h1db, *h2db, *t1b, *t2b;
    float *Z, *recon, *w, *loss;
    cudaGetSymbolAddress((void**)&Abf,   g_Abf);
    cudaGetSymbolAddress((void**)&We1b,  g_We1b);
    cudaGetSymbolAddress((void**)&We2b,  g_We2b);
    cudaGetSymbolAddress((void**)&We3b,  g_We3b);
    cudaGetSymbolAddress((void**)&Wd1b,  g_Wd1b);
    cudaGetSymbolAddress((void**)&Wd2b,  g_Wd2b);
    cudaGetSymbolAddress((void**)&Wd3b,  g_Wd3b);
    cudaGetSymbolAddress((void**)&H1b,   g_H1b);
    cudaGetSymbolAddress((void**)&H2b,   g_H2b);
    cudaGetSymbolAddress((void**)&Z,     g_Z);
    cudaGetSymbolAddress((void**)&dzb,   g_dzb);
    cudaGetSymbolAddress((void**)&zcb,   g_zcb);
    cudaGetSymbolAddress((void**)&h1db,  g_h1db);
    cudaGetSymbolAddress((void**)&h2db,  g_h2db);
    cudaGetSymbolAddress((void**)&recon, g_recon);
    cudaGetSymbolAddress((void**)&t1b,   g_t1b);
    cudaGetSymbolAddress((void**)&t2b,   g_t2b);
    cudaGetSymbolAddress((void**)&w,     g_w);
    cudaGetSymbolAddress((void**)&loss,  g_loss);

    cudaFuncSetAttribute(mma_gemm<EPI_BIAS_RELU_BF>, cudaFuncAttributeMaxDynamicSharedMemorySize, SMEM_DYN);
    cudaFuncSetAttribute(mma_gemm<EPI_BIAS_F32>,     cudaFuncAttributeMaxDynamicSharedMemorySize, SMEM_DYN);
    cudaFuncSetAttribute(mma_gemm<EPI_MASK_BF>,      cudaFuncAttributeMaxDynamicSharedMemorySize, SMEM_DYN);
    cudaFuncSetAttribute(mma_gemm<EPI_LOSS>,         cudaFuncAttributeMaxDynamicSharedMemorySize, SMEM_DYN);

    const dim3 blk(256);
    auto cgrid = [](int n) { return dim3((n / 4 + 255) / 256); };
    auto ggrid = [](int M, int N) { return dim3(N / 128, M / 128); };

    // conversions to bf16
    f2bf_k<<<cgrid(RTOT * D_DIM), blk>>>(x_nn, Abf, RTOT * D_DIM);
    f2bf_k<<<cgrid(BS * D_DIM), blk>>>(x_c, Abf + (size_t)RTOT * D_DIM, BS * D_DIM);
    f2bf_k<<<cgrid(D_DIM * H_DIM), blk>>>(We1, We1b, D_DIM * H_DIM);
    f2bf_k<<<cgrid(H_DIM * H_DIM), blk>>>(We2, We2b, H_DIM * H_DIM);
    f2bf_k<<<cgrid(H_DIM * Z_DIM), blk>>>(We3, We3b, H_DIM * Z_DIM);
    f2bf_k<<<cgrid(Z_DIM * H_DIM), blk>>>(Wd1, Wd1b, Z_DIM * H_DIM);
    f2bf_k<<<cgrid(H_DIM * H_DIM), blk>>>(Wd2, Wd2b, H_DIM * H_DIM);
    f2bf_k<<<cgrid(H_DIM * D_DIM), blk>>>(Wd3, Wd3b, H_DIM * D_DIM);

    // encoder (x_nn ++ x_c merged, M = 4224)
    mma_gemm<EPI_BIAS_RELU_BF><<<ggrid(MENC, H_DIM), blk, SMEM_DYN>>>(
        Abf, We1b, H1b, MENC, H_DIM, D_DIM, be1, nullptr, nullptr, nullptr, nullptr, nullptr);
    mma_gemm<EPI_BIAS_RELU_BF><<<ggrid(MENC, H_DIM), blk, SMEM_DYN>>>(
        H1b, We2b, H2b, MENC, H_DIM, H_DIM, be2, nullptr, nullptr, nullptr, nullptr, nullptr);
    gemm_n32_bf<<<MENC / 8, blk>>>(H2b, We3b, be3, Z, H_DIM);

    // tangents, weights, loss init
    dz_k<<<(RTOT * Z_DIM + BS * Z_DIM) / 256, blk>>>(Z, dzb, zcb);
    weights_k<<<RTOT, blk>>>(x_c, x_nn, w);
    zero_k<<<1, 1>>>(loss);

    // decoder at z_c: activations (ReLU masks) + recon
    mma_gemm<EPI_BIAS_RELU_BF><<<ggrid(BS, H_DIM), blk, SMEM_DYN>>>(
        zcb, Wd1b, h1db, BS, H_DIM, Z_DIM, bd1, nullptr, nullptr, nullptr, nullptr, nullptr);
    mma_gemm<EPI_BIAS_RELU_BF><<<ggrid(BS, H_DIM), blk, SMEM_DYN>>>(
        h1db, Wd2b, h2db, BS, H_DIM, H_DIM, bd2, nullptr, nullptr, nullptr, nullptr, nullptr);
    mma_gemm<EPI_BIAS_F32><<<ggrid(BS, D_DIM), blk, SMEM_DYN>>>(
        h2db, Wd3b, recon, BS, D_DIM, H_DIM, bd3, nullptr, nullptr, nullptr, nullptr, nullptr);

    // JVP chain (hess == 0 exactly for ReLU MLP)
    mma_gemm<EPI_MASK_BF><<<ggrid(RTOT, H_DIM), blk, SMEM_DYN>>>(
        dzb, Wd1b, t1b, RTOT, H_DIM, Z_DIM, nullptr, h1db, nullptr, nullptr, nullptr, nullptr);
    mma_gemm<EPI_MASK_BF><<<ggrid(RTOT, H_DIM), blk, SMEM_DYN>>>(
        t1b, Wd2b, t2b, RTOT, H_DIM, H_DIM, nullptr, h2db, nullptr, nullptr, nullptr, nullptr);
    // final GEMM with fused weighted squared-error reduction (jac never stored)
    mma_gemm<EPI_LOSS><<<ggrid(RTOT, D_DIM), blk, SMEM_DYN>>>(
        t2b, Wd3b, nullptr, RTOT, D_DIM, H_DIM, nullptr, nullptr, x_nn, recon, w, loss);

    final_k<<<1, 1>>>(loss, out);
}